// round 6
// baseline (speedup 1.0000x reference)
#include <cuda_runtime.h>
#include <cuda_bf16.h>

// quantizer: out[i] = center[argmin_m |x[i] - center[m]|]
// (forward value of w_bias + W_soft == W_hard exactly; softmax cancels)
//
// R6: uniform-grid LUT. Sorted centers c[0..15], midpoints t[0..14].
// Grid of B bins of width w over [t0 - w, t14 + w]; bin b = (a, a+w] holds
//   (tt, c_lo) where tt = the single threshold in (a, a+w] (else +INF),
//   c_lo = c[count(t <= a)].  c_hi(b) == c_lo(b+1) by construction.
// Element: b = clamp((max(x,lo)-lo)*invw); e=lut[b]; out = x>e.t ? lut[b+1].c : e.c
// => ~7 ALU + 2 LDS per element (vs ~12 ALU + 2 LDS for the binary search).
// Builder detects >=2 thresholds in one bin (or degenerate centers) and falls
// back to the exact 4-level binary-search path (uniform branch).

#define N_CENTERS 16
#define NBINS 2048

__device__ __forceinline__ float lookup_bs(float xv, const float* s,
                                           float t1, float t3, float t5, float t7,
                                           float t9, float t11, float t13)
{
    bool p1 = xv > t7;
    float ta = p1 ? t11 : t3;
    bool p2 = xv > ta;
    float tbl = p2 ? t5  : t1;
    float tbh = p2 ? t13 : t9;
    float tb  = p1 ? tbh : tbl;
    bool p3 = xv > tb;
    int j = (p1 ? 8 : 0) + (p2 ? 4 : 0) + (p3 ? 2 : 0);
    float tc = s[j];
    j += (xv > tc) ? 1 : 0;
    return s[16 + j];
}

__global__ __launch_bounds__(256) void quantizer_kernel(
    const float4* __restrict__ x4,
    const float* __restrict__ center,
    float4* __restrict__ out4,
    int n4)
{
    // s[0..14]: midpoint thresholds (ascending), s[16..31]: sorted centers
    __shared__ float s[32];
    __shared__ float2 lut[NBINS + 1];
    __shared__ int collide;

    if (threadIdx.x == 0) collide = 0;
    if (threadIdx.x < N_CENTERS) {
        float ci = __ldg(&center[threadIdx.x]);
        int rank = 0;
#pragma unroll
        for (int m = 0; m < N_CENTERS; m++) {
            float cm = __ldg(&center[m]);
            rank += (cm < ci) || (cm == ci && m < (int)threadIdx.x);
        }
        s[16 + rank] = ci;
    }
    __syncthreads();
    if (threadIdx.x < N_CENTERS - 1) {
        s[threadIdx.x] = 0.5f * (s[16 + threadIdx.x] + s[17 + threadIdx.x]);
    }
    __syncthreads();

    // ---- Build the LUT ----
    float span = s[14] - s[0];
    float w = span / (float)(NBINS - 2);
    float lo = s[0] - w;                 // grid start; bin b = (lo+b*w, lo+(b+1)*w]
    if (threadIdx.x == 0) {
        if (!(span > 0.0f) || !isfinite(span)) collide = 1;  // degenerate -> fallback
    }
    for (int b = threadIdx.x; b < NBINS + 1; b += blockDim.x) {
        float a  = lo + (float)b * w;
        float a2 = lo + (float)(b + 1) * w;
        int ja = 0, jb = 0;
#pragma unroll
        for (int k = 0; k < N_CENTERS - 1; k++) {
            ja += (s[k] <= a);
            jb += (s[k] <= a2);
        }
        int nin = jb - ja;               // thresholds in (a, a2]
        float tt = (nin == 1) ? s[ja] : __int_as_float(0x7f800000); // +INF
        if (nin > 1) collide = 1;        // benign race: any write sets it
        lut[b] = make_float2(tt, s[16 + ja]);
    }
    __syncthreads();

    const float t1 = s[1],  t3 = s[3],  t5 = s[5],  t7 = s[7];
    const float t9 = s[9],  t11 = s[11], t13 = s[13];
    const float invw = 1.0f / w;
    const int fallback = collide;

    const int S = gridDim.x * blockDim.x;
    int i = blockIdx.x * blockDim.x + threadIdx.x;

    if (!fallback) {
        // ---- LUT fast path ----
        for (; i + 7 * S < n4; i += 8 * S) {
            float4 v[8];
#pragma unroll
            for (int u = 0; u < 8; u++) v[u] = x4[i + u * S];
#pragma unroll
            for (int u = 0; u < 8; u++) {
                float r[4] = {v[u].x, v[u].y, v[u].z, v[u].w};
#pragma unroll
                for (int k = 0; k < 4; k++) {
                    float xc = fmaxf(r[k], lo);
                    int b = (int)((xc - lo) * invw);
                    b = min(b, NBINS - 1);
                    float2 e = lut[b];
                    float chi = lut[b + 1].y;
                    r[k] = (xc > e.x) ? chi : e.y;
                }
                v[u] = make_float4(r[0], r[1], r[2], r[3]);
            }
#pragma unroll
            for (int u = 0; u < 8; u++) __stcs(&out4[i + u * S], v[u]);
        }
        for (; i < n4; i += S) {
            float4 v = x4[i];
            float r[4] = {v.x, v.y, v.z, v.w};
#pragma unroll
            for (int k = 0; k < 4; k++) {
                float xc = fmaxf(r[k], lo);
                int b = (int)((xc - lo) * invw);
                b = min(b, NBINS - 1);
                float2 e = lut[b];
                float chi = lut[b + 1].y;
                r[k] = (xc > e.x) ? chi : e.y;
            }
            __stcs(&out4[i], make_float4(r[0], r[1], r[2], r[3]));
        }
    } else {
        // ---- Exact binary-search fallback ----
        for (; i < n4; i += S) {
            float4 v = x4[i];
            float4 o;
            o.x = lookup_bs(v.x, s, t1,t3,t5,t7,t9,t11,t13);
            o.y = lookup_bs(v.y, s, t1,t3,t5,t7,t9,t11,t13);
            o.z = lookup_bs(v.z, s, t1,t3,t5,t7,t9,t11,t13);
            o.w = lookup_bs(v.w, s, t1,t3,t5,t7,t9,t11,t13);
            __stcs(&out4[i], o);
        }
    }
}

extern "C" void kernel_launch(void* const* d_in, const int* in_sizes, int n_in,
                              void* d_out, int out_size) {
    const float* x = (const float*)d_in[0];
    const float* center = (const float*)d_in[1];
    float* out = (float*)d_out;

    int n = in_sizes[0];          // 16,777,216
    int n4 = n / 4;               // 4,194,304 float4s

    const int threads = 256;
    // 2048 * 256 threads * 8 float4 = 4,194,304 -> exactly one unrolled
    // iteration per thread for the expected shape.
    const int blocks = 2048;

    quantizer_kernel<<<blocks, threads>>>(
        (const float4*)x, center, (float4*)out, n4);
}